// round 16
// baseline (speedup 1.0000x reference)
#include <cuda_runtime.h>
#include <cuda_fp16.h>
#include <cfloat>
#include <cstdint>
#include <cstddef>

#define B_  2
#define T_  16
#define NP  1024
#define KNN 16
#define TOUT 14
#define C0 6
#define C1 64
#define C2 128
#define C3 256
#define EPSV 1e-5f

#define P1 (B_*T_*NP*KNN)
#define PM (B_*T_*NP)
#define PT (B_*TOUT*NP)

// ---------------- scratch ----------------
__device__ float g_feats[(size_t)P1*C0];
__device__ float g_curs[(size_t)B_*T_*NP*3];
__device__ float g_h1[(size_t)P1*C2];
__device__ float g_xm[(size_t)PM*C3];
__device__ float g_y[(size_t)PT*C3];
__device__ float g_pA[(P1/128)*C3];
__device__ float g_pB[(P1/128)*C3];
__device__ float g_scale[4*256];
__device__ float g_shift[4*256];
__device__ __half g_w2x[2*256*64];
__device__ __half g_wtx[12*256*64];
__device__ __half g_xmx[(size_t)PM*C3*2];

#define SWZ(x) ((x) ^ (((x) >> 3) & 0x70))

__device__ __forceinline__ uint32_t smem_u32(const void* p) {
    uint32_t a;
    asm("{ .reg .u64 t; cvta.to.shared.u64 t, %1; cvt.u32.u64 %0, t; }" : "=r"(a) : "l"(p));
    return a;
}
__device__ __forceinline__ uint32_t pkh(float a, float b) {
    __half2 h = __floats2half2_rn(a, b);
    return *reinterpret_cast<uint32_t*>(&h);
}
__device__ __forceinline__ void ldm_x4(uint32_t addr, uint32_t& r0, uint32_t& r1,
                                       uint32_t& r2, uint32_t& r3) {
    asm volatile("ldmatrix.sync.aligned.m8n8.x4.shared.b16 {%0,%1,%2,%3}, [%4];"
                 : "=r"(r0), "=r"(r1), "=r"(r2), "=r"(r3) : "r"(addr));
}
__device__ __forceinline__ void mma16816h(float* d, const uint32_t* a, const uint32_t* b) {
    asm volatile("mma.sync.aligned.m16n8k16.row.col.f32.f16.f16.f32 "
        "{%0,%1,%2,%3}, {%4,%5,%6,%7}, {%8,%9}, {%0,%1,%2,%3};"
        : "+f"(d[0]), "+f"(d[1]), "+f"(d[2]), "+f"(d[3])
        : "r"(a[0]), "r"(a[1]), "r"(a[2]), "r"(a[3]), "r"(b[0]), "r"(b[1]));
}
__device__ __forceinline__ void cpasync16(uint32_t saddr, const void* g) {
    asm volatile("cp.async.cg.shared.global [%0], [%1], 16;" :: "r"(saddr), "l"(g));
}
#define CP_COMMIT() asm volatile("cp.async.commit_group;" ::: "memory")
#define CP_WAIT(n)  asm volatile("cp.async.wait_group %0;" :: "n"(n) : "memory")

__device__ __forceinline__ float shfl_sum3(float v) {
    v += __shfl_xor_sync(0xffffffffu, v, 4);
    v += __shfl_xor_sync(0xffffffffu, v, 8);
    v += __shfl_xor_sync(0xffffffffu, v, 16);
    return v;
}
__device__ __forceinline__ float shfl_max3(float v) {
    v = fmaxf(v, __shfl_xor_sync(0xffffffffu, v, 4));
    v = fmaxf(v, __shfl_xor_sync(0xffffffffu, v, 8));
    v = fmaxf(v, __shfl_xor_sync(0xffffffffu, v, 16));
    return v;
}

// ---------------- stage 1a: trajectory pass ----------------
__global__ __launch_bounds__(256) void traj_kernel(const float* __restrict__ pts)
{
    __shared__ float spts[NP*3];
    int tid = threadIdx.x;
    int w = tid >> 5, lane = tid & 31;
    int gid = blockIdx.x*8 + w;
    int b = gid >> 10, i = gid & 1023;

    float cx = pts[((size_t)(b*T_)*NP + i)*3 + 0];
    float cy = pts[((size_t)(b*T_)*NP + i)*3 + 1];
    float cz = pts[((size_t)(b*T_)*NP + i)*3 + 2];

    for (int t = 0; t < T_; t++) {
        const float* pt = pts + (size_t)(b*T_ + t)*NP*3;
        for (int e = tid; e < NP*3; e += 256) spts[e] = pt[e];
        __syncthreads();
        if (lane == 0) {
            float* c = g_curs + ((size_t)(b*T_ + t)*NP + i)*3;
            c[0] = cx; c[1] = cy; c[2] = cz;
        }
        float bv = FLT_MAX; int bj = NP;
        #pragma unroll
        for (int m = 0; m < NP/32; m++) {
            int j = lane + m*32;
            float dx = cx - spts[j*3+0];
            float dy = cy - spts[j*3+1];
            float dz = cz - spts[j*3+2];
            float v = dx*dx + dy*dy + dz*dz;
            if (v < bv) { bv = v; bj = j; }
        }
        #pragma unroll
        for (int off = 16; off; off >>= 1) {
            float ov = __shfl_xor_sync(0xffffffffu, bv, off);
            int   oj = __shfl_xor_sync(0xffffffffu, bj, off);
            if (ov < bv || (ov == bv && oj < bj)) { bv = ov; bj = oj; }
        }
        cx = spts[bj*3+0]; cy = spts[bj*3+1]; cz = spts[bj*3+2];
        __syncthreads();
    }
}

// ---------------- stage 1b: parallel top-16 (R13 version, no moment fusion) --
#define TK_PAD 33
__global__ __launch_bounds__(256) void topk_kernel(const float* __restrict__ pts)
{
    extern __shared__ float sm[];
    float* spts = sm;
    float* d2a  = sm + 3072;
    int*   selw = (int*)(sm + 3072 + 8*TK_PAD*32);

    int tid = threadIdx.x;
    int w = tid >> 5, lane = tid & 31;
    int bt  = blockIdx.x >> 7;
    int grp = blockIdx.x & 127;
    int b = bt >> 4, t = bt & 15;
    int n = grp*8 + w;

    const float* pt = pts + (size_t)(b*T_ + t)*NP*3;
    const float* pp = pts + (size_t)(b*T_ + (t == 0 ? 0 : t-1))*NP*3;
    for (int e = tid; e < NP*3; e += 256) spts[e] = pt[e];
    __syncthreads();

    const float* cq = g_curs + ((size_t)bt*NP + n)*3;
    float cx = cq[0], cy = cq[1], cz = cq[2];
    const float* aq = g_curs + ((size_t)(b*T_ + 1)*NP + n)*3;
    float ax = aq[0], ay = aq[1], az = aq[2];

    float* dw = d2a + w*(TK_PAD*32);
    #pragma unroll
    for (int m = 0; m < 32; m++) {
        int j = lane + 32*m;
        float dx = cx - spts[j*3+0];
        float dy = cy - spts[j*3+1];
        float dz = cz - spts[j*3+2];
        dw[lane*TK_PAD + m] = dx*dx + dy*dy + dz*dz;
    }
    __syncwarp();
    float segV = FLT_MAX; int segJ = NP;
    #pragma unroll
    for (int m = 0; m < 32; m++) {
        float v = dw[m*TK_PAD + lane];
        if (v < segV) { segV = v; segJ = lane*32 + m; }
    }

    for (int k = 0; k < KNN; k++) {
        float gv = segV; int gj = segJ;
        #pragma unroll
        for (int off = 16; off; off >>= 1) {
            float ov = __shfl_xor_sync(0xffffffffu, gv, off);
            int   oj = __shfl_xor_sync(0xffffffffu, gj, off);
            if (ov < gv || (ov == gv && oj < gj)) { gv = ov; gj = oj; }
        }
        if (lane == 0) selw[w*KNN + k] = gj;
        int s = gj >> 5;
        if (lane == (gj & 31)) dw[(gj & 31)*TK_PAD + s] = FLT_MAX;
        __syncwarp();
        float v = dw[lane*TK_PAD + s];
        int j = 32*s + lane;
        #pragma unroll
        for (int off = 16; off; off >>= 1) {
            float ov = __shfl_xor_sync(0xffffffffu, v, off);
            int   oj = __shfl_xor_sync(0xffffffffu, j, off);
            if (ov < v || (ov == v && oj < j)) { v = ov; j = oj; }
        }
        if (lane == s) { segV = v; segJ = j; }
    }
    __syncwarp();

    size_t basef = ((size_t)bt*NP + n) * KNN;
    if (lane < KNN) {
        int sj = selw[w*KNN + lane];
        float* dst = g_feats + (basef + lane)*6;
        dst[0] = pp[sj*3+0]; dst[1] = pp[sj*3+1]; dst[2] = pp[sj*3+2];
        dst[3] = spts[sj*3+0] - ax; dst[4] = spts[sj*3+1] - ay; dst[5] = spts[sj*3+2] - az;
    }
}

// ---------------- feats moments (512 blocks x 1024 rows) ----------------
__global__ __launch_bounds__(256) void moment_kernel()
{
    int tid = threadIdx.x;
    float s[6] = {}, m[21] = {};
    size_t base = (size_t)blockIdx.x * 1024;
    for (int i = 0; i < 4; i++) {
        size_t r = base + i*256 + tid;
        const float* fp = g_feats + r*6;
        float x[6];
        #pragma unroll
        for (int j = 0; j < 6; j++) x[j] = fp[j];
        int idx = 0;
        #pragma unroll
        for (int j = 0; j < 6; j++) {
            s[j] += x[j];
            #pragma unroll
            for (int k = j; k < 6; k++) m[idx++] += x[j]*x[k];
        }
    }
    __shared__ float red[8][27];
    int w = tid >> 5, lane = tid & 31;
    #pragma unroll
    for (int off = 16; off; off >>= 1) {
        #pragma unroll
        for (int j = 0; j < 6; j++) s[j] += __shfl_xor_sync(0xffffffffu, s[j], off);
        #pragma unroll
        for (int q = 0; q < 21; q++) m[q] += __shfl_xor_sync(0xffffffffu, m[q], off);
    }
    if (lane == 0) {
        #pragma unroll
        for (int j = 0; j < 6; j++) red[w][j] = s[j];
        #pragma unroll
        for (int q = 0; q < 21; q++) red[w][6+q] = m[q];
    }
    __syncthreads();
    if (tid < 27) {
        float a = 0.f;
        #pragma unroll
        for (int r = 0; r < 8; r++) a += red[r][tid];
        g_pA[blockIdx.x*32 + tid] = a;
    }
}

// ---------------- analytic BN0 fold ----------------
__global__ void fold0_kernel(const float* __restrict__ W0, const float* __restrict__ B0,
                             const float* __restrict__ g, const float* __restrict__ be)
{
    __shared__ double M[27];
    int tid = threadIdx.x;
    if (tid < 27) {
        double a = 0.0;
        for (int r = 0; r < 512; r++) a += (double)g_pA[r*32 + tid];
        M[tid] = a / (double)P1;
    }
    __syncthreads();
    if (tid < 64) {
        double w[6];
        #pragma unroll
        for (int j = 0; j < 6; j++) w[j] = (double)W0[tid*6 + j];
        double b = (double)B0[tid];
        double wm = 0.0;
        #pragma unroll
        for (int j = 0; j < 6; j++) wm += w[j]*M[j];
        double mean = wm + b;
        double E2 = 0.0;
        int idx = 0;
        for (int j = 0; j < 6; j++)
            for (int k = j; k < 6; k++) {
                double t = w[j]*w[k]*M[6+idx];
                E2 += (j == k) ? t : 2.0*t;
                idx++;
            }
        E2 += 2.0*b*wm + b*b;
        double var = E2 - mean*mean;
        float sc = g[tid] * rsqrtf((float)var + EPSV);
        g_scale[tid] = sc;
        g_shift[tid] = be[tid] - (float)mean * sc;
    }
}

// ---------------- fold BN stats slots 1-3 ----------------
__global__ void fold_kernel(int nblk, int C, float cnt,
                            const float* __restrict__ g, const float* __restrict__ be,
                            int slot)
{
    int c = blockIdx.x;
    double s = 0.0, q = 0.0;
    for (int r = threadIdx.x; r < nblk; r += 256) {
        s += (double)g_pA[r*C + c];
        q += (double)g_pB[r*C + c];
    }
    __shared__ double sh[512];
    sh[threadIdx.x] = s; sh[256 + threadIdx.x] = q;
    __syncthreads();
    for (int o = 128; o; o >>= 1) {
        if (threadIdx.x < o) {
            sh[threadIdx.x] += sh[threadIdx.x + o];
            sh[256 + threadIdx.x] += sh[256 + threadIdx.x + o];
        }
        __syncthreads();
    }
    if (threadIdx.x == 0) {
        double m = sh[0] / (double)cnt;
        double v = sh[256] / (double)cnt - m*m;
        float sc = g[c] * rsqrtf((float)v + EPSV);
        g_scale[slot*256 + c] = sc;
        g_shift[slot*256 + c] = be[c] - (float)m * sc;
    }
}

// ---------------- combined weight prep (w2 + wt) ----------------
__global__ void prep_kernel(const float* __restrict__ W2, const float* __restrict__ wt,
                            __half* __restrict__ w2x)
{
    int i = blockIdx.x*256 + threadIdx.x;
    if (i < C3*C2) {
        int n = i / C2, c = i % C2;
        int chunk = c >> 6, k = c & 63;
        w2x[(size_t)chunk*(C3*64) + (SWZ(n*128 + k*2) >> 1)] = __float2half_rn(W2[i]);
    } else {
        int j = i - C3*C2;
        if (j < C3*C3*3) {
            int dt = j % 3;
            int c  = (j / 3) % C3;
            int o  = j / (3*C3);
            int chunk = dt*4 + (c >> 6);
            int k = c & 63;
            g_wtx[(size_t)chunk*(C3*64) + (SWZ(o*128 + k*2) >> 1)] = __float2half_rn(wt[j]);
        }
    }
}

// ---------------- cvt for tconv input (xm -> split fp16 tiles) --------------
template<int CIN>
__global__ __launch_bounds__(256) void cvt_kernel(const float* __restrict__ src,
                                                  __half* __restrict__ dst,
                                                  int affSlot)
{
    __shared__ float sS[64], sC[64];
    int tid = threadIdx.x;
    if (tid < 64) {
        sS[tid] = g_scale[affSlot*256 + blockIdx.y*64 + tid];
        sC[tid] = g_shift[affSlot*256 + blockIdx.y*64 + tid];
    }
    __syncthreads();
    char* out = (char*)dst + ((size_t)blockIdx.x*gridDim.y + blockIdx.y)*32768;
    const float* Ab = src + (size_t)blockIdx.x*128*CIN + blockIdx.y*64;
    #pragma unroll
    for (int i = 0; i < 8; i++) {
        int f = tid + i*256;
        int row = f >> 4;
        int k = (f & 15) * 4;
        float4 v = *(const float4*)(Ab + (size_t)row*CIN + k);
        v.x = fmaxf(fmaf(v.x, sS[k+0], sC[k+0]), 0.f);
        v.y = fmaxf(fmaf(v.y, sS[k+1], sC[k+1]), 0.f);
        v.z = fmaxf(fmaf(v.z, sS[k+2], sC[k+2]), 0.f);
        v.w = fmaxf(fmaf(v.w, sS[k+3], sC[k+3]), 0.f);
        float h0 = __half2float(__float2half_rn(v.x));
        float h1 = __half2float(__float2half_rn(v.y));
        float h2 = __half2float(__float2half_rn(v.z));
        float h3 = __half2float(__float2half_rn(v.w));
        uint32_t off = SWZ((uint32_t)(row*128 + k*2));
        *(uint2*)(out + off)         = make_uint2(pkh(v.x, v.y), pkh(v.z, v.w));
        *(uint2*)(out + 16384 + off) = make_uint2(pkh(v.x - h0, v.y - h1), pkh(v.z - h2, v.w - h3));
    }
}

// ---------------- gemm1: feats -> inline layer0 -> 64->128 GEMM --------------
#define OFFG_W    0
#define OFFG_F0   16384
#define OFFG_F1   19456
#define OFFG_AHI  22528
#define OFFG_ALO  38912
#define OFFG_W0S  55296
#define OFFG_B0S  56832
#define OFFG_SS   57088
#define OFFG_SC   57344
#define OFFG_BIAS 57600
#define OFFG_PS   58112
#define OFFG_PQ   59136
#define SMBG1     60160
#define G1_TILES  4

__global__ __launch_bounds__(256, 2) void mma_gemm1(
    const float* __restrict__ F, const float* __restrict__ W0,
    const float* __restrict__ B0, const float* __restrict__ W,
    const float* __restrict__ bias,
    float* __restrict__ out, float* __restrict__ pA, float* __restrict__ pB)
{
    extern __shared__ __align__(1024) char smem[];
    const int tid = threadIdx.x;
    const int wid = tid >> 5, lane = tid & 31;
    const int warpRow = wid & 1, warpCol = wid >> 1;
    const uint32_t sb32 = smem_u32(smem);

    float* sS = (float*)(smem + OFFG_SS);
    float* sC = (float*)(smem + OFFG_SC);
    float* sbias = (float*)(smem + OFFG_BIAS);
    float* w0s = (float*)(smem + OFFG_W0S);
    float* b0s = (float*)(smem + OFFG_B0S);
    if (tid < 64) { sS[tid] = g_scale[tid]; sC[tid] = g_shift[tid]; b0s[tid] = B0[tid]; }
    if (tid < 128) sbias[tid] = bias[tid];
    for (int i = tid; i < 384; i += 256) {
        int ch = i & 63, j = i >> 6;
        w0s[ch + 64*j] = W0[ch*6 + j];
    }
    for (int i = tid; i < 128*64; i += 256) {
        int n = i >> 6, c = i & 63;
        *(__half*)(smem + OFFG_W + SWZ(n*128 + c*2)) = __float2half_rn(W[i]);
    }
    if (tid < 192) {
        const char* Fb = (const char*)(F + (size_t)(blockIdx.x*G1_TILES)*128*6);
        cpasync16(sb32 + OFFG_F0 + tid*16, Fb + tid*16);
    }
    CP_COMMIT();
    __syncthreads();

    const int k0 = (tid & 15) * 4;
    float wr[6][4], b0r[4], sSr[4], sCr[4];
    #pragma unroll
    for (int q = 0; q < 4; q++) {
        b0r[q] = b0s[k0 + q]; sSr[q] = sS[k0 + q]; sCr[q] = sC[k0 + q];
        #pragma unroll
        for (int j = 0; j < 6; j++) wr[j][q] = w0s[(k0 + q) + 64*j];
    }

    for (int tile = 0; tile < G1_TILES; tile++) {
        int rowBase = (blockIdx.x*G1_TILES + tile)*128;
        uint32_t fbase = (tile & 1) ? OFFG_F1 : OFFG_F0;
        CP_WAIT(0);
        __syncthreads();
        if (tile + 1 < G1_TILES && tid < 192) {
            uint32_t fnext = ((tile + 1) & 1) ? OFFG_F1 : OFFG_F0;
            const char* Fb = (const char*)(F + (size_t)(blockIdx.x*G1_TILES + tile + 1)*128*6);
            cpasync16(sb32 + fnext + tid*16, Fb + tid*16);
        }
        if (tile + 1 < G1_TILES) CP_COMMIT();
        #pragma unroll
        for (int i = 0; i < 8; i++) {
            int f = tid + i*256;
            int row = f >> 4;
            const float* fr = (const float*)(smem + fbase) + row*6;
            float x0 = fr[0], x1 = fr[1], x2 = fr[2], x3 = fr[3], x4 = fr[4], x5 = fr[5];
            float v[4];
            #pragma unroll
            for (int q = 0; q < 4; q++) {
                float a = b0r[q];
                a = fmaf(x0, wr[0][q], a);
                a = fmaf(x1, wr[1][q], a);
                a = fmaf(x2, wr[2][q], a);
                a = fmaf(x3, wr[3][q], a);
                a = fmaf(x4, wr[4][q], a);
                a = fmaf(x5, wr[5][q], a);
                v[q] = fmaxf(fmaf(a, sSr[q], sCr[q]), 0.f);
            }
            float h0 = __half2float(__float2half_rn(v[0]));
            float h1 = __half2float(__float2half_rn(v[1]));
            float h2 = __half2float(__float2half_rn(v[2]));
            float h3 = __half2float(__float2half_rn(v[3]));
            uint32_t off = SWZ((uint32_t)(row*128 + k0*2));
            *(uint2*)(smem + OFFG_AHI + off) = make_uint2(pkh(v[0], v[1]), pkh(v[2], v[3]));
            *(uint2*)(smem + OFFG_ALO + off) = make_uint2(pkh(v[0] - h0, v[1] - h1), pkh(v[2] - h2, v[3] - h3));
        }
        __syncthreads();
        float acc[4][4][4] = {};
        #pragma unroll
        for (int ks = 0; ks < 4; ks++) {
            uint32_t bh[4][2];
            #pragma unroll
            for (int nt2 = 0; nt2 < 2; nt2++) {
                uint32_t roff = (uint32_t)((warpCol*32 + nt2*16 + ((lane>>4)<<3) + (lane&7))*128
                                           + ks*32 + (((lane>>3)&1)<<4));
                ldm_x4(sb32 + OFFG_W + SWZ(roff), bh[nt2*2][0], bh[nt2*2][1], bh[nt2*2+1][0], bh[nt2*2+1][1]);
            }
            #pragma unroll
            for (int mt = 0; mt < 4; mt++) {
                uint32_t roff = (uint32_t)((warpRow*64 + mt*16 + (lane&15))*128
                                           + ks*32 + ((lane>>4)<<4));
                uint32_t ah[4], al[4];
                ldm_x4(sb32 + OFFG_AHI + SWZ(roff), ah[0], ah[1], ah[2], ah[3]);
                ldm_x4(sb32 + OFFG_ALO + SWZ(roff), al[0], al[1], al[2], al[3]);
                #pragma unroll
                for (int nt = 0; nt < 4; nt++) mma16816h(acc[mt][nt], ah, bh[nt]);
                #pragma unroll
                for (int nt = 0; nt < 4; nt++) mma16816h(acc[mt][nt], al, bh[nt]);
            }
        }
        #pragma unroll
        for (int nt = 0; nt < 4; nt++) {
            int cl = warpCol*32 + nt*8 + (lane&3)*2;
            float b0v = sbias[cl], b1v = sbias[cl+1];
            #pragma unroll
            for (int mt = 0; mt < 4; mt++) {
                acc[mt][nt][0] += b0v; acc[mt][nt][1] += b1v;
                acc[mt][nt][2] += b0v; acc[mt][nt][3] += b1v;
            }
        }
        float* ps = (float*)(smem + OFFG_PS);
        float* pq = (float*)(smem + OFFG_PQ);
        #pragma unroll
        for (int nt = 0; nt < 4; nt++) {
            float s0 = 0.f, s1 = 0.f, q0 = 0.f, q1 = 0.f;
            #pragma unroll
            for (int mt = 0; mt < 4; mt++) {
                float c0 = acc[mt][nt][0], c1 = acc[mt][nt][1];
                float c2 = acc[mt][nt][2], c3 = acc[mt][nt][3];
                s0 += c0 + c2; s1 += c1 + c3;
                q0 += c0*c0 + c2*c2; q1 += c1*c1 + c3*c3;
            }
            s0 = shfl_sum3(s0); s1 = shfl_sum3(s1);
            q0 = shfl_sum3(q0); q1 = shfl_sum3(q1);
            if (lane < 4) {
                int cl = warpCol*32 + nt*8 + lane*2;
                ps[warpRow*128 + cl] = s0; ps[warpRow*128 + cl + 1] = s1;
                pq[warpRow*128 + cl] = q0; pq[warpRow*128 + cl + 1] = q1;
            }
        }
        #pragma unroll
        for (int mt = 0; mt < 4; mt++) {
            int r0 = rowBase + warpRow*64 + mt*16 + (lane >> 2);
            #pragma unroll
            for (int nt = 0; nt < 4; nt++) {
                int cl = warpCol*32 + nt*8 + (lane&3)*2;
                *(float2*)&out[(size_t)r0*C2 + cl]     = make_float2(acc[mt][nt][0], acc[mt][nt][1]);
                *(float2*)&out[(size_t)(r0+8)*C2 + cl] = make_float2(acc[mt][nt][2], acc[mt][nt][3]);
            }
        }
        __syncthreads();
        if (tid < 128) {
            pA[(size_t)(blockIdx.x*G1_TILES + tile)*C2 + tid] = ps[tid] + ps[128 + tid];
            pB[(size_t)(blockIdx.x*G1_TILES + tile)*C2 + tid] = pq[tid] + pq[128 + tid];
        }
    }
}

// ---------------- gemm2: raw fp32 h1 -> inline cvt -> 128->256 + maxpool -----
// 512 threads, 16 warps: warpRow = wid&3 (32 rows), warpCol = wid>>2 (64 cols).
// W (both K-chunks) resident in smem; RAW double-buffered; AHI/ALO single.
#define OFF2_RAW0 0
#define OFF2_RAW1 32768
#define OFF2_AHI  65536
#define OFF2_ALO  81920
#define OFF2_WS   98304
#define OFF2_SS   163840
#define OFF2_SC   164352
#define OFF2_BIAS 164864
#define OFF2_PS   165888
#define OFF2_PQ   169984
#define SMB2      174080

__global__ __launch_bounds__(512, 1) void mma_gemm2(
    const float* __restrict__ A, const __half* __restrict__ Wx,
    const float* __restrict__ bias,
    float* __restrict__ out, float* __restrict__ pA, float* __restrict__ pB)
{
    extern __shared__ __align__(1024) char smem[];
    const int tid = threadIdx.x;
    const int wid = tid >> 5, lane = tid & 31;
    const int warpRow = wid & 3, warpCol = wid >> 2;
    const int rowBase = blockIdx.x * 128;
    const uint32_t sb32 = smem_u32(smem);

    float* sS = (float*)(smem + OFF2_SS);
    float* sC = (float*)(smem + OFF2_SC);
    float* sbias = (float*)(smem + OFF2_BIAS);
    if (tid < 128) { sS[tid] = g_scale[256 + tid]; sC[tid] = g_shift[256 + tid]; }
    if (tid < 256) sbias[tid] = bias[tid];

    // W both chunks: 64 KB
    #pragma unroll
    for (int i = 0; i < 8; i++) {
        int o = (tid + i*512) * 16;
        cpasync16(sb32 + OFF2_WS + o, (const char*)Wx + o);
    }
    // RAW chunk 0 (cols 0..63, row stride 128 floats)
    #pragma unroll
    for (int i = 0; i < 4; i++) {
        int f = tid + i*512;
        int row = f >> 4, seg = f & 15;
        cpasync16(sb32 + OFF2_RAW0 + row*256 + seg*16,
                  (const char*)(A + (size_t)(rowBase + row)*C2) + seg*16);
    }
    CP_COMMIT();
    __syncthreads();   // sS/sC/bias visible

    float acc[2][8][4] = {};
    for (int chunk = 0; chunk < 2; chunk++) {
        CP_WAIT(0);
        __syncthreads();
        uint32_t rawb = chunk ? OFF2_RAW1 : OFF2_RAW0;
        // convert: 128x64 -> AHI/ALO
        #pragma unroll
        for (int i = 0; i < 4; i++) {
            int f = tid + i*512;
            int row = f >> 4;
            int k = (f & 15) * 4;
            float4 v = *(const float4*)(smem + rawb + (row*64 + k)*4);
            int ch = chunk*64 + k;
            v.x = fmaxf(fmaf(v.x, sS[ch+0], sC[ch+0]), 0.f);
            v.y = fmaxf(fmaf(v.y, sS[ch+1], sC[ch+1]), 0.f);
            v.z = fmaxf(fmaf(v.z, sS[ch+2], sC[ch+2]), 0.f);
            v.w = fmaxf(fmaf(v.w, sS[ch+3], sC[ch+3]), 0.f);
            float h0 = __half2float(__float2half_rn(v.x));
            float h1 = __half2float(__float2half_rn(v.y));
            float h2 = __half2float(__float2half_rn(v.z));
            float h3 = __half2float(__float2half_rn(v.w));
            uint32_t off = SWZ((uint32_t)(row*128 + k*2));
            *(uint2*)(smem + OFF2_AHI + off) = make_uint2(pkh(v.x, v.y), pkh(v.z, v.w));
            *(uint2*)(smem + OFF2_ALO + off) = make_uint2(pkh(v.x - h0, v.y - h1), pkh(v.z - h2, v.w - h3));
        }
        __syncthreads();
        if (chunk == 0) {
            #pragma unroll
            for (int i = 0; i < 4; i++) {
                int f = tid + i*512;
                int row = f >> 4, seg = f & 15;
                cpasync16(sb32 + OFF2_RAW1 + row*256 + seg*16,
                          (const char*)(A + (size_t)(rowBase + row)*C2 + 64) + seg*16);
            }
            CP_COMMIT();
        }
        uint32_t wb = OFF2_WS + chunk*32768;
        #pragma unroll
        for (int ks = 0; ks < 4; ks++) {
            uint32_t bh[8][2];
            #pragma unroll
            for (int nt2 = 0; nt2 < 4; nt2++) {
                uint32_t roff = (uint32_t)((warpCol*64 + nt2*16 + ((lane>>4)<<3) + (lane&7))*128
                                           + ks*32 + (((lane>>3)&1)<<4));
                ldm_x4(sb32 + wb + SWZ(roff), bh[nt2*2][0], bh[nt2*2][1], bh[nt2*2+1][0], bh[nt2*2+1][1]);
            }
            #pragma unroll
            for (int mt = 0; mt < 2; mt++) {
                uint32_t roff = (uint32_t)((warpRow*32 + mt*16 + (lane&15))*128
                                           + ks*32 + ((lane>>4)<<4));
                uint32_t ah[4], al[4];
                ldm_x4(sb32 + OFF2_AHI + SWZ(roff), ah[0], ah[1], ah[2], ah[3]);
                ldm_x4(sb32 + OFF2_ALO + SWZ(roff), al[0], al[1], al[2], al[3]);
                #pragma unroll
                for (int nt = 0; nt < 8; nt++) mma16816h(acc[mt][nt], ah, bh[nt]);
                #pragma unroll
                for (int nt = 0; nt < 8; nt++) mma16816h(acc[mt][nt], al, bh[nt]);
            }
        }
        __syncthreads();   // AHI/ALO free for next convert
    }

    // -------- epilogue: bias, BN partials (pre-max), maxpool --------
    #pragma unroll
    for (int nt = 0; nt < 8; nt++) {
        int cl = warpCol*64 + nt*8 + (lane&3)*2;
        float b0 = sbias[cl], b1 = sbias[cl+1];
        #pragma unroll
        for (int mt = 0; mt < 2; mt++) {
            acc[mt][nt][0] += b0; acc[mt][nt][1] += b1;
            acc[mt][nt][2] += b0; acc[mt][nt][3] += b1;
        }
    }
    float* ps = (float*)(smem + OFF2_PS);
    float* pq = (float*)(smem + OFF2_PQ);
    #pragma unroll
    for (int nt = 0; nt < 8; nt++) {
        float s0 = 0.f, s1 = 0.f, q0 = 0.f, q1 = 0.f;
        #pragma unroll
        for (int mt = 0; mt < 2; mt++) {
            float c0 = acc[mt][nt][0], c1 = acc[mt][nt][1];
            float c2 = acc[mt][nt][2], c3 = acc[mt][nt][3];
            s0 += c0 + c2; s1 += c1 + c3;
            q0 += c0*c0 + c2*c2; q1 += c1*c1 + c3*c3;
        }
        s0 = shfl_sum3(s0); s1 = shfl_sum3(s1);
        q0 = shfl_sum3(q0); q1 = shfl_sum3(q1);
        if (lane < 4) {
            int cl = warpCol*64 + nt*8 + lane*2;
            ps[warpRow*256 + cl] = s0; ps[warpRow*256 + cl + 1] = s1;
            pq[warpRow*256 + cl] = q0; pq[warpRow*256 + cl + 1] = q1;
        }
    }
    // maxpool: each mt tile = one 16-row (btn) group
    #pragma unroll
    for (int mt = 0; mt < 2; mt++) {
        int grow = (rowBase >> 4) + warpRow*2 + mt;
        #pragma unroll
        for (int nt = 0; nt < 8; nt++) {
            float m0 = shfl_max3(fmaxf(acc[mt][nt][0], acc[mt][nt][2]));
            float m1 = shfl_max3(fmaxf(acc[mt][nt][1], acc[mt][nt][3]));
            if (lane < 4) {
                int cl = warpCol*64 + nt*8 + lane*2;
                *(float2*)&out[(size_t)grow*C3 + cl] = make_float2(m0, m1);
            }
        }
    }
    __syncthreads();
    if (tid < 256) {
        pA[(size_t)blockIdx.x*C3 + tid] = ps[tid] + ps[256 + tid] + ps[512 + tid] + ps[768 + tid];
        pB[(size_t)blockIdx.x*C3 + tid] = pq[tid] + pq[256 + tid] + pq[512 + tid] + pq[768 + tid];
    }
}

// ---------------- general GEMM (tconv, MODE 2) ----------------
#define OFF_A0   0
#define OFF_A1   32768
#define OFF_W0   65536
#define OFF_W1   81920
#define OFF_BIAS 98304
#define OFF_PS   98816
#define OFF_PQ   99840
#define SMB_GEMM 100864

template<int COUT, int NCHUNK, int MODE>
__global__ __launch_bounds__(256, 2) void mma_gemm(
    const __half* __restrict__ Ax, const __half* __restrict__ Wx,
    const float* __restrict__ bias,
    float* __restrict__ out, float* __restrict__ pA, float* __restrict__ pB)
{
    extern __shared__ __align__(1024) char smem[];
    const int tid = threadIdx.x;
    const int wid = tid >> 5, lane = tid & 31;
    const int warpRow = wid & 1, warpCol = wid >> 1;
    const int rowBlk  = blockIdx.y;
    const int rowBase = rowBlk * 128;
    const int colBase = blockIdx.x * 128;
    const uint32_t sb32 = smem_u32(smem);

    float* sbias = (float*)(smem + OFF_BIAS);
    if (tid < 128) sbias[tid] = bias[colBase + tid];

    int bb = 0, to = 0, n0 = 0;
    if (MODE == 2) { bb = rowBase/(TOUT*NP); to = (rowBase/NP) % TOUT; n0 = rowBase % NP; }

    auto a_tile = [&](int chunk) -> size_t {
        if (MODE == 2) {
            int dt = chunk >> 2, kc = chunk & 3;
            int rb = (bb*T_ + to + dt)*(NP/128) + (n0 >> 7);
            return ((size_t)rb*4 + kc)*32768;
        }
        return ((size_t)rowBlk*NCHUNK + chunk)*32768;
    };
    auto issue = [&](int chunk) {
        uint32_t abase = (chunk & 1) ? OFF_A1 : OFF_A0;
        uint32_t wbase = (chunk & 1) ? OFF_W1 : OFF_W0;
        const char* As = (const char*)Ax + a_tile(chunk);
        #pragma unroll
        for (int i = 0; i < 8; i++) {
            int o = (tid + i*256) * 16;
            cpasync16(sb32 + abase + o, As + o);
        }
        const char* Wp = (const char*)(Wx + (size_t)chunk*((size_t)COUT*64) + (size_t)colBase*64);
        #pragma unroll
        for (int i = 0; i < 4; i++) {
            int o = (tid + i*256) * 16;
            cpasync16(sb32 + wbase + o, Wp + o);
        }
        CP_COMMIT();
    };

    float acc[4][4][4] = {};

    issue(0);
    if (NCHUNK > 1) issue(1);

    for (int chunk = 0; chunk < NCHUNK; chunk++) {
        if (chunk + 1 < NCHUNK) { CP_WAIT(1); } else { CP_WAIT(0); }
        __syncthreads();
        uint32_t abase = (chunk & 1) ? OFF_A1 : OFF_A0;
        uint32_t wbase = (chunk & 1) ? OFF_W1 : OFF_W0;
        #pragma unroll
        for (int ks = 0; ks < 4; ks++) {
            uint32_t bh[4][2];
            #pragma unroll
            for (int nt2 = 0; nt2 < 2; nt2++) {
                uint32_t roff = (uint32_t)((warpCol*32 + nt2*16 + ((lane>>4)<<3) + (lane&7))*128
                                           + ks*32 + (((lane>>3)&1)<<4));
                ldm_x4(sb32 + wbase + SWZ(roff), bh[nt2*2][0], bh[nt2*2][1], bh[nt2*2+1][0], bh[nt2*2+1][1]);
            }
            #pragma unroll
            for (int mt = 0; mt < 4; mt++) {
                uint32_t roff = (uint32_t)((warpRow*64 + mt*16 + (lane&15))*128
                                           + ks*32 + ((lane>>4)<<4));
                uint32_t ah[4], al[4];
                ldm_x4(sb32 + abase + SWZ(roff), ah[0], ah[1], ah[2], ah[3]);
                ldm_x4(sb32 + abase + 16384 + SWZ(roff), al[0], al[1], al[2], al[3]);
                #pragma unroll
                for (int nt = 0; nt < 4; nt++) mma16816h(acc[mt][nt], ah, bh[nt]);
                #pragma unroll
                for (int nt = 0; nt < 4; nt++) mma16816h(acc[mt][nt], al, bh[nt]);
            }
        }
        __syncthreads();
        if (chunk + 2 < NCHUNK) issue(chunk + 2);
    }

    // -------- epilogue --------
    #pragma unroll
    for (int nt = 0; nt < 4; nt++) {
        int cl = warpCol*32 + nt*8 + (lane&3)*2;
        float b0 = sbias[cl], b1 = sbias[cl+1];
        #pragma unroll
        for (int mt = 0; mt < 4; mt++) {
            acc[mt][nt][0] += b0; acc[mt][nt][1] += b1;
            acc[mt][nt][2] += b0; acc[mt][nt][3] += b1;
        }
    }
    float* ps = (float*)(smem + OFF_PS);
    float* pq = (float*)(smem + OFF_PQ);
    #pragma unroll
    for (int nt = 0; nt < 4; nt++) {
        float s0 = 0.f, s1 = 0.f, q0 = 0.f, q1 = 0.f;
        #pragma unroll
        for (int mt = 0; mt < 4; mt++) {
            float c0 = acc[mt][nt][0], c1 = acc[mt][nt][1];
            float c2 = acc[mt][nt][2], c3 = acc[mt][nt][3];
            s0 += c0 + c2; s1 += c1 + c3;
            q0 += c0*c0 + c2*c2; q1 += c1*c1 + c3*c3;
        }
        s0 = shfl_sum3(s0); s1 = shfl_sum3(s1);
        q0 = shfl_sum3(q0); q1 = shfl_sum3(q1);
        if (lane < 4) {
            int cl = warpCol*32 + nt*8 + lane*2;
            ps[warpRow*128 + cl] = s0; ps[warpRow*128 + cl + 1] = s1;
            pq[warpRow*128 + cl] = q0; pq[warpRow*128 + cl + 1] = q1;
        }
    }
    {
        float* tile = (float*)smem;
        __syncthreads();
        #pragma unroll
        for (int mt = 0; mt < 4; mt++) {
            int r0 = warpRow*64 + mt*16 + (lane >> 2);
            #pragma unroll
            for (int nt = 0; nt < 4; nt++) {
                int cl = warpCol*32 + nt*8 + (lane&3)*2;
                *(float2*)&tile[(r0)*132 + cl]   = make_float2(acc[mt][nt][0], acc[mt][nt][1]);
                *(float2*)&tile[(r0+8)*132 + cl] = make_float2(acc[mt][nt][2], acc[mt][nt][3]);
            }
        }
        __syncthreads();
        int r = tid >> 1, half = (tid & 1)*64;
        const float* src = tile + r*132 + half;
        float* dst = out + (size_t)(rowBase + r)*COUT + colBase + half;
        #pragma unroll
        for (int i = 0; i < 16; i++)
            *(float4*)(dst + i*4) = *(const float4*)(src + i*4);
    }
    __syncthreads();
    if (tid < 128) {
        pA[(size_t)rowBlk*COUT + colBase + tid] = ps[tid] + ps[128 + tid];
        pB[(size_t)rowBlk*COUT + colBase + tid] = pq[tid] + pq[128 + tid];
    }
}

// ---------------- final BN + relu -> output ----------------
__global__ void final_kernel(float* __restrict__ out)
{
    int i = blockIdx.x*blockDim.x + threadIdx.x;
    if (i < PT*C3) {
        int c = i & 255;
        out[i] = fmaxf(g_y[i]*g_scale[3*256 + c] + g_shift[3*256 + c], 0.f);
    }
}

// ---------------- launch ----------------
extern "C" void kernel_launch(void* const* d_in, const int* in_sizes, int n_in,
                              void* d_out, int out_size)
{
    (void)in_sizes; (void)n_in; (void)out_size;
    const float* pts = (const float*)d_in[0];
    const float* w0  = (const float*)d_in[1];
    const float* b0  = (const float*)d_in[2];
    const float* gg0 = (const float*)d_in[3];
    const float* be0 = (const float*)d_in[4];
    const float* w1  = (const float*)d_in[5];
    const float* b1  = (const float*)d_in[6];
    const float* gg1 = (const float*)d_in[7];
    const float* be1 = (const float*)d_in[8];
    const float* w2  = (const float*)d_in[9];
    const float* b2  = (const float*)d_in[10];
    const float* gg2 = (const float*)d_in[11];
    const float* be2 = (const float*)d_in[12];
    const float* wt  = (const float*)d_in[13];
    const float* bt  = (const float*)d_in[14];
    const float* ggt = (const float*)d_in[15];
    const float* bet = (const float*)d_in[16];
    float* out = (float*)d_out;

    float *dfe = nullptr, *dh1 = nullptr, *dxm = nullptr, *dy = nullptr;
    float *dpA = nullptr, *dpB = nullptr;
    __half *dw2x = nullptr, *dwtx = nullptr, *dxmx = nullptr;
    cudaGetSymbolAddress((void**)&dfe, g_feats);
    cudaGetSymbolAddress((void**)&dh1, g_h1);
    cudaGetSymbolAddress((void**)&dxm, g_xm);
    cudaGetSymbolAddress((void**)&dy, g_y);
    cudaGetSymbolAddress((void**)&dpA, g_pA);
    cudaGetSymbolAddress((void**)&dpB, g_pB);
    cudaGetSymbolAddress((void**)&dw2x, g_w2x);
    cudaGetSymbolAddress((void**)&dwtx, g_wtx);
    cudaGetSymbolAddress((void**)&dxmx, g_xmx);

    const int SMB_TOPK = (3072 + 8*TK_PAD*32)*4 + 8*KNN*4;
    static bool attr_set = false;
    if (!attr_set) {
        cudaFuncSetAttribute(topk_kernel,        cudaFuncAttributeMaxDynamicSharedMemorySize, SMB_TOPK);
        cudaFuncSetAttribute(mma_gemm1,          cudaFuncAttributeMaxDynamicSharedMemorySize, SMBG1);
        cudaFuncSetAttribute(mma_gemm2,          cudaFuncAttributeMaxDynamicSharedMemorySize, SMB2);
        cudaFuncSetAttribute(mma_gemm<256,12,2>, cudaFuncAttributeMaxDynamicSharedMemorySize, SMB_GEMM);
        attr_set = true;
    }

    prep_kernel<<<(C3*C2 + C3*C3*3 + 255)/256, 256>>>(w2, wt, dw2x);
    traj_kernel<<<B_*NP/8, 256>>>(pts);
    topk_kernel<<<B_*T_*128, 256, SMB_TOPK>>>(pts);
    moment_kernel<<<512, 256>>>();
    fold0_kernel<<<1, 64>>>(w0, b0, gg0, be0);

    mma_gemm1<<<P1/128/G1_TILES, 256, SMBG1>>>(dfe, w0, b0, w1, b1, dh1, dpA, dpB);
    fold_kernel<<<C2, 256>>>(P1/128, C2, (float)P1, gg1, be1, 1);

    mma_gemm2<<<P1/128, 512, SMB2>>>(dh1, dw2x, b2, dxm, dpA, dpB);
    fold_kernel<<<C3, 256>>>(P1/128, C3, (float)P1, gg2, be2, 2);

    cvt_kernel<C3><<<dim3(PM/128, 4), 256>>>(dxm, dxmx, 2);
    mma_gemm<256,12,2><<<dim3(2, PT/128), 256, SMB_GEMM>>>(dxmx, dwtx, bt, dy, dpA, dpB);
    fold_kernel<<<C3, 256>>>(PT/128, C3, (float)PT, ggt, bet, 3);

    final_kernel<<<(PT*C3 + 255)/256, 256>>>(out);
}

// round 17
// speedup vs baseline: 1.0542x; 1.0542x over previous
#include <cuda_runtime.h>
#include <cuda_fp16.h>
#include <cfloat>
#include <cstdint>
#include <cstddef>

#define B_  2
#define T_  16
#define NP  1024
#define KNN 16
#define TOUT 14
#define C0 6
#define C1 64
#define C2 128
#define C3 256
#define EPSV 1e-5f

#define P1 (B_*T_*NP*KNN)
#define PM (B_*T_*NP)
#define PT (B_*TOUT*NP)

// ---------------- scratch ----------------
__device__ float g_feats[(size_t)P1*C0];
__device__ float g_curs[(size_t)B_*T_*NP*3];
__device__ float g_h1[(size_t)P1*C2];
__device__ float g_xm[(size_t)PM*C3];
__device__ float g_y[(size_t)PT*C3];
__device__ float g_pA[(P1/128)*C3];
__device__ float g_pB[(P1/128)*C3];
__device__ float g_scale[4*256];
__device__ float g_shift[4*256];
__device__ __half g_w2x[2*256*64];
__device__ __half g_wtx[12*256*64];
__device__ __half g_h1x[(size_t)P1*C2*2];
__device__ __half g_xmx[(size_t)PM*C3*2];

#define SWZ(x) ((x) ^ (((x) >> 3) & 0x70))

__device__ __forceinline__ uint32_t smem_u32(const void* p) {
    uint32_t a;
    asm("{ .reg .u64 t; cvta.to.shared.u64 t, %1; cvt.u32.u64 %0, t; }" : "=r"(a) : "l"(p));
    return a;
}
__device__ __forceinline__ uint32_t pkh(float a, float b) {
    __half2 h = __floats2half2_rn(a, b);
    return *reinterpret_cast<uint32_t*>(&h);
}
__device__ __forceinline__ void ldm_x4(uint32_t addr, uint32_t& r0, uint32_t& r1,
                                       uint32_t& r2, uint32_t& r3) {
    asm volatile("ldmatrix.sync.aligned.m8n8.x4.shared.b16 {%0,%1,%2,%3}, [%4];"
                 : "=r"(r0), "=r"(r1), "=r"(r2), "=r"(r3) : "r"(addr));
}
__device__ __forceinline__ void mma16816h(float* d, const uint32_t* a, const uint32_t* b) {
    asm volatile("mma.sync.aligned.m16n8k16.row.col.f32.f16.f16.f32 "
        "{%0,%1,%2,%3}, {%4,%5,%6,%7}, {%8,%9}, {%0,%1,%2,%3};"
        : "+f"(d[0]), "+f"(d[1]), "+f"(d[2]), "+f"(d[3])
        : "r"(a[0]), "r"(a[1]), "r"(a[2]), "r"(a[3]), "r"(b[0]), "r"(b[1]));
}
__device__ __forceinline__ void cpasync16(uint32_t saddr, const void* g) {
    asm volatile("cp.async.cg.shared.global [%0], [%1], 16;" :: "r"(saddr), "l"(g));
}
#define CP_COMMIT() asm volatile("cp.async.commit_group;" ::: "memory")
#define CP_WAIT(n)  asm volatile("cp.async.wait_group %0;" :: "n"(n) : "memory")

__device__ __forceinline__ float shfl_sum3(float v) {
    v += __shfl_xor_sync(0xffffffffu, v, 4);
    v += __shfl_xor_sync(0xffffffffu, v, 8);
    v += __shfl_xor_sync(0xffffffffu, v, 16);
    return v;
}
__device__ __forceinline__ float shfl_max3(float v) {
    v = fmaxf(v, __shfl_xor_sync(0xffffffffu, v, 4));
    v = fmaxf(v, __shfl_xor_sync(0xffffffffu, v, 8));
    v = fmaxf(v, __shfl_xor_sync(0xffffffffu, v, 16));
    return v;
}

// ---------------- stage 1a: trajectory pass ----------------
__global__ __launch_bounds__(256) void traj_kernel(const float* __restrict__ pts)
{
    __shared__ float spts[NP*3];
    int tid = threadIdx.x;
    int w = tid >> 5, lane = tid & 31;
    int gid = blockIdx.x*8 + w;
    int b = gid >> 10, i = gid & 1023;

    float cx = pts[((size_t)(b*T_)*NP + i)*3 + 0];
    float cy = pts[((size_t)(b*T_)*NP + i)*3 + 1];
    float cz = pts[((size_t)(b*T_)*NP + i)*3 + 2];

    for (int t = 0; t < T_; t++) {
        const float* pt = pts + (size_t)(b*T_ + t)*NP*3;
        for (int e = tid; e < NP*3; e += 256) spts[e] = pt[e];
        __syncthreads();
        if (lane == 0) {
            float* c = g_curs + ((size_t)(b*T_ + t)*NP + i)*3;
            c[0] = cx; c[1] = cy; c[2] = cz;
        }
        float bv = FLT_MAX; int bj = NP;
        #pragma unroll
        for (int m = 0; m < NP/32; m++) {
            int j = lane + m*32;
            float dx = cx - spts[j*3+0];
            float dy = cy - spts[j*3+1];
            float dz = cz - spts[j*3+2];
            float v = dx*dx + dy*dy + dz*dz;
            if (v < bv) { bv = v; bj = j; }
        }
        #pragma unroll
        for (int off = 16; off; off >>= 1) {
            float ov = __shfl_xor_sync(0xffffffffu, bv, off);
            int   oj = __shfl_xor_sync(0xffffffffu, bj, off);
            if (ov < bv || (ov == bv && oj < bj)) { bv = ov; bj = oj; }
        }
        cx = spts[bj*3+0]; cy = spts[bj*3+1]; cz = spts[bj*3+2];
        __syncthreads();
    }
}

// ---------------- stage 1b: parallel top-16, segment minima ------------------
#define TK_PAD 33
__global__ __launch_bounds__(256) void topk_kernel(const float* __restrict__ pts)
{
    extern __shared__ float sm[];
    float* spts = sm;
    float* d2a  = sm + 3072;
    int*   selw = (int*)(sm + 3072 + 8*TK_PAD*32);

    int tid = threadIdx.x;
    int w = tid >> 5, lane = tid & 31;
    int bt  = blockIdx.x >> 7;
    int grp = blockIdx.x & 127;
    int b = bt >> 4, t = bt & 15;
    int n = grp*8 + w;

    const float* pt = pts + (size_t)(b*T_ + t)*NP*3;
    const float* pp = pts + (size_t)(b*T_ + (t == 0 ? 0 : t-1))*NP*3;
    for (int e = tid; e < NP*3; e += 256) spts[e] = pt[e];
    __syncthreads();

    const float* cq = g_curs + ((size_t)bt*NP + n)*3;
    float cx = cq[0], cy = cq[1], cz = cq[2];
    const float* aq = g_curs + ((size_t)(b*T_ + 1)*NP + n)*3;
    float ax = aq[0], ay = aq[1], az = aq[2];

    float* dw = d2a + w*(TK_PAD*32);
    #pragma unroll
    for (int m = 0; m < 32; m++) {
        int j = lane + 32*m;
        float dx = cx - spts[j*3+0];
        float dy = cy - spts[j*3+1];
        float dz = cz - spts[j*3+2];
        dw[lane*TK_PAD + m] = dx*dx + dy*dy + dz*dz;
    }
    __syncwarp();
    float segV = FLT_MAX; int segJ = NP;
    #pragma unroll
    for (int m = 0; m < 32; m++) {
        float v = dw[m*TK_PAD + lane];
        if (v < segV) { segV = v; segJ = lane*32 + m; }
    }

    for (int k = 0; k < KNN; k++) {
        float gv = segV; int gj = segJ;
        #pragma unroll
        for (int off = 16; off; off >>= 1) {
            float ov = __shfl_xor_sync(0xffffffffu, gv, off);
            int   oj = __shfl_xor_sync(0xffffffffu, gj, off);
            if (ov < gv || (ov == gv && oj < gj)) { gv = ov; gj = oj; }
        }
        if (lane == 0) selw[w*KNN + k] = gj;
        int s = gj >> 5;
        if (lane == (gj & 31)) dw[(gj & 31)*TK_PAD + s] = FLT_MAX;
        __syncwarp();
        float v = dw[lane*TK_PAD + s];
        int j = 32*s + lane;
        #pragma unroll
        for (int off = 16; off; off >>= 1) {
            float ov = __shfl_xor_sync(0xffffffffu, v, off);
            int   oj = __shfl_xor_sync(0xffffffffu, j, off);
            if (ov < v || (ov == v && oj < j)) { v = ov; j = oj; }
        }
        if (lane == s) { segV = v; segJ = j; }
    }
    __syncwarp();

    size_t basef = ((size_t)bt*NP + n) * KNN;
    if (lane < KNN) {
        int sj = selw[w*KNN + lane];
        float* dst = g_feats + (basef + lane)*6;
        dst[0] = pp[sj*3+0]; dst[1] = pp[sj*3+1]; dst[2] = pp[sj*3+2];
        dst[3] = spts[sj*3+0] - ax; dst[4] = spts[sj*3+1] - ay; dst[5] = spts[sj*3+2] - az;
    }
}

// ---------------- feats moments (512 blocks x 1024 rows) ----------------
__global__ __launch_bounds__(256) void moment_kernel()
{
    int tid = threadIdx.x;
    float s[6] = {}, m[21] = {};
    size_t base = (size_t)blockIdx.x * 1024;
    for (int i = 0; i < 4; i++) {
        size_t r = base + i*256 + tid;
        const float* fp = g_feats + r*6;
        float x[6];
        #pragma unroll
        for (int j = 0; j < 6; j++) x[j] = fp[j];
        int idx = 0;
        #pragma unroll
        for (int j = 0; j < 6; j++) {
            s[j] += x[j];
            #pragma unroll
            for (int k = j; k < 6; k++) m[idx++] += x[j]*x[k];
        }
    }
    __shared__ float red[8][27];
    int w = tid >> 5, lane = tid & 31;
    #pragma unroll
    for (int off = 16; off; off >>= 1) {
        #pragma unroll
        for (int j = 0; j < 6; j++) s[j] += __shfl_xor_sync(0xffffffffu, s[j], off);
        #pragma unroll
        for (int q = 0; q < 21; q++) m[q] += __shfl_xor_sync(0xffffffffu, m[q], off);
    }
    if (lane == 0) {
        #pragma unroll
        for (int j = 0; j < 6; j++) red[w][j] = s[j];
        #pragma unroll
        for (int q = 0; q < 21; q++) red[w][6+q] = m[q];
    }
    __syncthreads();
    if (tid < 27) {
        float a = 0.f;
        #pragma unroll
        for (int r = 0; r < 8; r++) a += red[r][tid];
        g_pA[blockIdx.x*32 + tid] = a;
    }
}

// ---------------- analytic BN0 fold ----------------
__global__ void fold0_kernel(const float* __restrict__ W0, const float* __restrict__ B0,
                             const float* __restrict__ g, const float* __restrict__ be)
{
    __shared__ double M[27];
    int tid = threadIdx.x;
    if (tid < 27) {
        double a = 0.0;
        for (int r = 0; r < 512; r++) a += (double)g_pA[r*32 + tid];
        M[tid] = a / (double)P1;
    }
    __syncthreads();
    if (tid < 64) {
        double w[6];
        #pragma unroll
        for (int j = 0; j < 6; j++) w[j] = (double)W0[tid*6 + j];
        double b = (double)B0[tid];
        double wm = 0.0;
        #pragma unroll
        for (int j = 0; j < 6; j++) wm += w[j]*M[j];
        double mean = wm + b;
        double E2 = 0.0;
        int idx = 0;
        for (int j = 0; j < 6; j++)
            for (int k = j; k < 6; k++) {
                double t = w[j]*w[k]*M[6+idx];
                E2 += (j == k) ? t : 2.0*t;
                idx++;
            }
        E2 += 2.0*b*wm + b*b;
        double var = E2 - mean*mean;
        float sc = g[tid] * rsqrtf((float)var + EPSV);
        g_scale[tid] = sc;
        g_shift[tid] = be[tid] - (float)mean * sc;
    }
}

// ---------------- fold BN stats slots 1-3 ----------------
__global__ void fold_kernel(int nblk, int C, float cnt,
                            const float* __restrict__ g, const float* __restrict__ be,
                            int slot)
{
    int c = blockIdx.x;
    double s = 0.0, q = 0.0;
    for (int r = threadIdx.x; r < nblk; r += 256) {
        s += (double)g_pA[r*C + c];
        q += (double)g_pB[r*C + c];
    }
    __shared__ double sh[512];
    sh[threadIdx.x] = s; sh[256 + threadIdx.x] = q;
    __syncthreads();
    for (int o = 128; o; o >>= 1) {
        if (threadIdx.x < o) {
            sh[threadIdx.x] += sh[threadIdx.x + o];
            sh[256 + threadIdx.x] += sh[256 + threadIdx.x + o];
        }
        __syncthreads();
    }
    if (threadIdx.x == 0) {
        double m = sh[0] / (double)cnt;
        double v = sh[256] / (double)cnt - m*m;
        float sc = g[c] * rsqrtf((float)v + EPSV);
        g_scale[slot*256 + c] = sc;
        g_shift[slot*256 + c] = be[c] - (float)m * sc;
    }
}

// ---------------- combined weight prep (w2 + wt) ----------------
__global__ void prep_kernel(const float* __restrict__ W2, const float* __restrict__ wt,
                            __half* __restrict__ w2x)
{
    int i = blockIdx.x*256 + threadIdx.x;
    if (i < C3*C2) {
        int n = i / C2, c = i % C2;
        int chunk = c >> 6, k = c & 63;
        w2x[(size_t)chunk*(C3*64) + (SWZ(n*128 + k*2) >> 1)] = __float2half_rn(W2[i]);
    } else {
        int j = i - C3*C2;
        if (j < C3*C3*3) {
            int dt = j % 3;
            int c  = (j / 3) % C3;
            int o  = j / (3*C3);
            int chunk = dt*4 + (c >> 6);
            int k = c & 63;
            g_wtx[(size_t)chunk*(C3*64) + (SWZ(o*128 + k*2) >> 1)] = __float2half_rn(wt[j]);
        }
    }
}

// ---------------- activation convert: affine+relu -> split fp16 tiles --------
template<int CIN>
__global__ __launch_bounds__(256) void cvt_kernel(const float* __restrict__ src,
                                                  __half* __restrict__ dst,
                                                  int affSlot)
{
    __shared__ float sS[64], sC[64];
    int tid = threadIdx.x;
    if (tid < 64) {
        sS[tid] = g_scale[affSlot*256 + blockIdx.y*64 + tid];
        sC[tid] = g_shift[affSlot*256 + blockIdx.y*64 + tid];
    }
    __syncthreads();
    char* out = (char*)dst + ((size_t)blockIdx.x*gridDim.y + blockIdx.y)*32768;
    const float* Ab = src + (size_t)blockIdx.x*128*CIN + blockIdx.y*64;
    #pragma unroll
    for (int i = 0; i < 8; i++) {
        int f = tid + i*256;
        int row = f >> 4;
        int k = (f & 15) * 4;
        float4 v = *(const float4*)(Ab + (size_t)row*CIN + k);
        v.x = fmaxf(fmaf(v.x, sS[k+0], sC[k+0]), 0.f);
        v.y = fmaxf(fmaf(v.y, sS[k+1], sC[k+1]), 0.f);
        v.z = fmaxf(fmaf(v.z, sS[k+2], sC[k+2]), 0.f);
        v.w = fmaxf(fmaf(v.w, sS[k+3], sC[k+3]), 0.f);
        float h0 = __half2float(__float2half_rn(v.x));
        float h1 = __half2float(__float2half_rn(v.y));
        float h2 = __half2float(__float2half_rn(v.z));
        float h3 = __half2float(__float2half_rn(v.w));
        uint32_t off = SWZ((uint32_t)(row*128 + k*2));
        *(uint2*)(out + off)         = make_uint2(pkh(v.x, v.y), pkh(v.z, v.w));
        *(uint2*)(out + 16384 + off) = make_uint2(pkh(v.x - h0, v.y - h1), pkh(v.z - h2, v.w - h3));
    }
}

// ---------------- gemm1: feats -> inline layer0 -> 64->128 GEMM --------------
#define OFFG_W    0
#define OFFG_F0   16384
#define OFFG_F1   19456
#define OFFG_AHI  22528
#define OFFG_ALO  38912
#define OFFG_W0S  55296
#define OFFG_B0S  56832
#define OFFG_SS   57088
#define OFFG_SC   57344
#define OFFG_BIAS 57600
#define OFFG_PS   58112
#define OFFG_PQ   59136
#define SMBG1     60160
#define G1_TILES  4

__global__ __launch_bounds__(256, 2) void mma_gemm1(
    const float* __restrict__ F, const float* __restrict__ W0,
    const float* __restrict__ B0, const float* __restrict__ W,
    const float* __restrict__ bias,
    float* __restrict__ out, float* __restrict__ pA, float* __restrict__ pB)
{
    extern __shared__ __align__(1024) char smem[];
    const int tid = threadIdx.x;
    const int wid = tid >> 5, lane = tid & 31;
    const int warpRow = wid & 1, warpCol = wid >> 1;
    const uint32_t sb32 = smem_u32(smem);

    float* sS = (float*)(smem + OFFG_SS);
    float* sC = (float*)(smem + OFFG_SC);
    float* sbias = (float*)(smem + OFFG_BIAS);
    float* w0s = (float*)(smem + OFFG_W0S);
    float* b0s = (float*)(smem + OFFG_B0S);
    if (tid < 64) { sS[tid] = g_scale[tid]; sC[tid] = g_shift[tid]; b0s[tid] = B0[tid]; }
    if (tid < 128) sbias[tid] = bias[tid];
    for (int i = tid; i < 384; i += 256) {
        int ch = i & 63, j = i >> 6;
        w0s[ch + 64*j] = W0[ch*6 + j];
    }
    for (int i = tid; i < 128*64; i += 256) {
        int n = i >> 6, c = i & 63;
        *(__half*)(smem + OFFG_W + SWZ(n*128 + c*2)) = __float2half_rn(W[i]);
    }
    if (tid < 192) {
        const char* Fb = (const char*)(F + (size_t)(blockIdx.x*G1_TILES)*128*6);
        cpasync16(sb32 + OFFG_F0 + tid*16, Fb + tid*16);
    }
    CP_COMMIT();
    __syncthreads();

    const int k0 = (tid & 15) * 4;
    float wr[6][4], b0r[4], sSr[4], sCr[4];
    #pragma unroll
    for (int q = 0; q < 4; q++) {
        b0r[q] = b0s[k0 + q]; sSr[q] = sS[k0 + q]; sCr[q] = sC[k0 + q];
        #pragma unroll
        for (int j = 0; j < 6; j++) wr[j][q] = w0s[(k0 + q) + 64*j];
    }

    for (int tile = 0; tile < G1_TILES; tile++) {
        int rowBase = (blockIdx.x*G1_TILES + tile)*128;
        uint32_t fbase = (tile & 1) ? OFFG_F1 : OFFG_F0;
        CP_WAIT(0);
        __syncthreads();
        if (tile + 1 < G1_TILES && tid < 192) {
            uint32_t fnext = ((tile + 1) & 1) ? OFFG_F1 : OFFG_F0;
            const char* Fb = (const char*)(F + (size_t)(blockIdx.x*G1_TILES + tile + 1)*128*6);
            cpasync16(sb32 + fnext + tid*16, Fb + tid*16);
        }
        if (tile + 1 < G1_TILES) CP_COMMIT();
        #pragma unroll
        for (int i = 0; i < 8; i++) {
            int f = tid + i*256;
            int row = f >> 4;
            const float* fr = (const float*)(smem + fbase) + row*6;
            float x0 = fr[0], x1 = fr[1], x2 = fr[2], x3 = fr[3], x4 = fr[4], x5 = fr[5];
            float v[4];
            #pragma unroll
            for (int q = 0; q < 4; q++) {
                float a = b0r[q];
                a = fmaf(x0, wr[0][q], a);
                a = fmaf(x1, wr[1][q], a);
                a = fmaf(x2, wr[2][q], a);
                a = fmaf(x3, wr[3][q], a);
                a = fmaf(x4, wr[4][q], a);
                a = fmaf(x5, wr[5][q], a);
                v[q] = fmaxf(fmaf(a, sSr[q], sCr[q]), 0.f);
            }
            float h0 = __half2float(__float2half_rn(v[0]));
            float h1 = __half2float(__float2half_rn(v[1]));
            float h2 = __half2float(__float2half_rn(v[2]));
            float h3 = __half2float(__float2half_rn(v[3]));
            uint32_t off = SWZ((uint32_t)(row*128 + k0*2));
            *(uint2*)(smem + OFFG_AHI + off) = make_uint2(pkh(v[0], v[1]), pkh(v[2], v[3]));
            *(uint2*)(smem + OFFG_ALO + off) = make_uint2(pkh(v[0] - h0, v[1] - h1), pkh(v[2] - h2, v[3] - h3));
        }
        __syncthreads();
        float acc[4][4][4] = {};
        #pragma unroll
        for (int ks = 0; ks < 4; ks++) {
            uint32_t bh[4][2];
            #pragma unroll
            for (int nt2 = 0; nt2 < 2; nt2++) {
                uint32_t roff = (uint32_t)((warpCol*32 + nt2*16 + ((lane>>4)<<3) + (lane&7))*128
                                           + ks*32 + (((lane>>3)&1)<<4));
                ldm_x4(sb32 + OFFG_W + SWZ(roff), bh[nt2*2][0], bh[nt2*2][1], bh[nt2*2+1][0], bh[nt2*2+1][1]);
            }
            #pragma unroll
            for (int mt = 0; mt < 4; mt++) {
                uint32_t roff = (uint32_t)((warpRow*64 + mt*16 + (lane&15))*128
                                           + ks*32 + ((lane>>4)<<4));
                uint32_t ah[4], al[4];
                ldm_x4(sb32 + OFFG_AHI + SWZ(roff), ah[0], ah[1], ah[2], ah[3]);
                ldm_x4(sb32 + OFFG_ALO + SWZ(roff), al[0], al[1], al[2], al[3]);
                #pragma unroll
                for (int nt = 0; nt < 4; nt++) mma16816h(acc[mt][nt], ah, bh[nt]);
                #pragma unroll
                for (int nt = 0; nt < 4; nt++) mma16816h(acc[mt][nt], al, bh[nt]);
            }
        }
        #pragma unroll
        for (int nt = 0; nt < 4; nt++) {
            int cl = warpCol*32 + nt*8 + (lane&3)*2;
            float b0v = sbias[cl], b1v = sbias[cl+1];
            #pragma unroll
            for (int mt = 0; mt < 4; mt++) {
                acc[mt][nt][0] += b0v; acc[mt][nt][1] += b1v;
                acc[mt][nt][2] += b0v; acc[mt][nt][3] += b1v;
            }
        }
        float* ps = (float*)(smem + OFFG_PS);
        float* pq = (float*)(smem + OFFG_PQ);
        #pragma unroll
        for (int nt = 0; nt < 4; nt++) {
            float s0 = 0.f, s1 = 0.f, q0 = 0.f, q1 = 0.f;
            #pragma unroll
            for (int mt = 0; mt < 4; mt++) {
                float c0 = acc[mt][nt][0], c1 = acc[mt][nt][1];
                float c2 = acc[mt][nt][2], c3 = acc[mt][nt][3];
                s0 += c0 + c2; s1 += c1 + c3;
                q0 += c0*c0 + c2*c2; q1 += c1*c1 + c3*c3;
            }
            s0 = shfl_sum3(s0); s1 = shfl_sum3(s1);
            q0 = shfl_sum3(q0); q1 = shfl_sum3(q1);
            if (lane < 4) {
                int cl = warpCol*32 + nt*8 + lane*2;
                ps[warpRow*128 + cl] = s0; ps[warpRow*128 + cl + 1] = s1;
                pq[warpRow*128 + cl] = q0; pq[warpRow*128 + cl + 1] = q1;
            }
        }
        #pragma unroll
        for (int mt = 0; mt < 4; mt++) {
            int r0 = rowBase + warpRow*64 + mt*16 + (lane >> 2);
            #pragma unroll
            for (int nt = 0; nt < 4; nt++) {
                int cl = warpCol*32 + nt*8 + (lane&3)*2;
                *(float2*)&out[(size_t)r0*C2 + cl]     = make_float2(acc[mt][nt][0], acc[mt][nt][1]);
                *(float2*)&out[(size_t)(r0+8)*C2 + cl] = make_float2(acc[mt][nt][2], acc[mt][nt][3]);
            }
        }
        __syncthreads();
        if (tid < 128) {
            pA[(size_t)(blockIdx.x*G1_TILES + tile)*C2 + tid] = ps[tid] + ps[128 + tid];
            pB[(size_t)(blockIdx.x*G1_TILES + tile)*C2 + tid] = pq[tid] + pq[128 + tid];
        }
    }
}

// ---------------- general GEMM: A pre-converted tiles, W fp16 plane ----------
#define OFF_A0   0
#define OFF_A1   32768
#define OFF_W0   65536
#define OFF_W1   81920
#define OFF_BIAS 98304
#define OFF_PS   98816
#define OFF_PQ   99840
#define SMB_GEMM 100864

template<int COUT, int NCHUNK, int MODE>
__global__ __launch_bounds__(256, 2) void mma_gemm(
    const __half* __restrict__ Ax, const __half* __restrict__ Wx,
    const float* __restrict__ bias,
    float* __restrict__ out, float* __restrict__ pA, float* __restrict__ pB)
{
    extern __shared__ __align__(1024) char smem[];
    const int tid = threadIdx.x;
    const int wid = tid >> 5, lane = tid & 31;
    const int warpRow = wid & 1, warpCol = wid >> 1;
    const int rowBlk  = blockIdx.y;
    const int rowBase = rowBlk * 128;
    const int colBase = blockIdx.x * 128;
    const uint32_t sb32 = smem_u32(smem);

    float* sbias = (float*)(smem + OFF_BIAS);
    if (tid < 128) sbias[tid] = bias[colBase + tid];

    int bb = 0, to = 0, n0 = 0;
    if (MODE == 2) { bb = rowBase/(TOUT*NP); to = (rowBase/NP) % TOUT; n0 = rowBase % NP; }

    auto a_tile = [&](int chunk) -> size_t {
        if (MODE == 2) {
            int dt = chunk >> 2, kc = chunk & 3;
            int rb = (bb*T_ + to + dt)*(NP/128) + (n0 >> 7);
            return ((size_t)rb*4 + kc)*32768;
        }
        return ((size_t)rowBlk*NCHUNK + chunk)*32768;
    };
    auto issue = [&](int chunk) {
        uint32_t abase = (chunk & 1) ? OFF_A1 : OFF_A0;
        uint32_t wbase = (chunk & 1) ? OFF_W1 : OFF_W0;
        const char* As = (const char*)Ax + a_tile(chunk);
        #pragma unroll
        for (int i = 0; i < 8; i++) {
            int o = (tid + i*256) * 16;
            cpasync16(sb32 + abase + o, As + o);
        }
        const char* Wp = (const char*)(Wx + (size_t)chunk*((size_t)COUT*64) + (size_t)colBase*64);
        #pragma unroll
        for (int i = 0; i < 4; i++) {
            int o = (tid + i*256) * 16;
            cpasync16(sb32 + wbase + o, Wp + o);
        }
        CP_COMMIT();
    };

    float acc[4][4][4] = {};

    issue(0);
    if (NCHUNK > 1) issue(1);

    for (int chunk = 0; chunk < NCHUNK; chunk++) {
        if (chunk + 1 < NCHUNK) { CP_WAIT(1); } else { CP_WAIT(0); }
        __syncthreads();
        uint32_t abase = (chunk & 1) ? OFF_A1 : OFF_A0;
        uint32_t wbase = (chunk & 1) ? OFF_W1 : OFF_W0;
        #pragma unroll
        for (int ks = 0; ks < 4; ks++) {
            uint32_t bh[4][2];
            #pragma unroll
            for (int nt2 = 0; nt2 < 2; nt2++) {
                uint32_t roff = (uint32_t)((warpCol*32 + nt2*16 + ((lane>>4)<<3) + (lane&7))*128
                                           + ks*32 + (((lane>>3)&1)<<4));
                ldm_x4(sb32 + wbase + SWZ(roff), bh[nt2*2][0], bh[nt2*2][1], bh[nt2*2+1][0], bh[nt2*2+1][1]);
            }
            #pragma unroll
            for (int mt = 0; mt < 4; mt++) {
                uint32_t roff = (uint32_t)((warpRow*64 + mt*16 + (lane&15))*128
                                           + ks*32 + ((lane>>4)<<4));
                uint32_t ah[4], al[4];
                ldm_x4(sb32 + abase + SWZ(roff), ah[0], ah[1], ah[2], ah[3]);
                ldm_x4(sb32 + abase + 16384 + SWZ(roff), al[0], al[1], al[2], al[3]);
                #pragma unroll
                for (int nt = 0; nt < 4; nt++) mma16816h(acc[mt][nt], ah, bh[nt]);
                #pragma unroll
                for (int nt = 0; nt < 4; nt++) mma16816h(acc[mt][nt], al, bh[nt]);
            }
        }
        __syncthreads();
        if (chunk + 2 < NCHUNK) issue(chunk + 2);
    }

    // -------- epilogue --------
    #pragma unroll
    for (int nt = 0; nt < 4; nt++) {
        int cl = warpCol*32 + nt*8 + (lane&3)*2;
        float b0 = sbias[cl], b1 = sbias[cl+1];
        #pragma unroll
        for (int mt = 0; mt < 4; mt++) {
            acc[mt][nt][0] += b0; acc[mt][nt][1] += b1;
            acc[mt][nt][2] += b0; acc[mt][nt][3] += b1;
        }
    }
    float* ps = (float*)(smem + OFF_PS);
    float* pq = (float*)(smem + OFF_PQ);
    #pragma unroll
    for (int nt = 0; nt < 4; nt++) {
        float s0 = 0.f, s1 = 0.f, q0 = 0.f, q1 = 0.f;
        #pragma unroll
        for (int mt = 0; mt < 4; mt++) {
            float c0 = acc[mt][nt][0], c1 = acc[mt][nt][1];
            float c2 = acc[mt][nt][2], c3 = acc[mt][nt][3];
            s0 += c0 + c2; s1 += c1 + c3;
            q0 += c0*c0 + c2*c2; q1 += c1*c1 + c3*c3;
        }
        s0 = shfl_sum3(s0); s1 = shfl_sum3(s1);
        q0 = shfl_sum3(q0); q1 = shfl_sum3(q1);
        if (lane < 4) {
            int cl = warpCol*32 + nt*8 + lane*2;
            ps[warpRow*128 + cl] = s0; ps[warpRow*128 + cl + 1] = s1;
            pq[warpRow*128 + cl] = q0; pq[warpRow*128 + cl + 1] = q1;
        }
    }
    if (MODE == 1) {
        #pragma unroll
        for (int mt = 0; mt < 4; mt++) {
            int grow = (rowBase >> 4) + warpRow*4 + mt;
            #pragma unroll
            for (int nt = 0; nt < 4; nt++) {
                float m0 = shfl_max3(fmaxf(acc[mt][nt][0], acc[mt][nt][2]));
                float m1 = shfl_max3(fmaxf(acc[mt][nt][1], acc[mt][nt][3]));
                if (lane < 4) {
                    int cl = colBase + warpCol*32 + nt*8 + lane*2;
                    *(float2*)&out[(size_t)grow*COUT + cl] = make_float2(m0, m1);
                }
            }
        }
    } else {
        float* tile = (float*)smem;
        __syncthreads();
        #pragma unroll
        for (int mt = 0; mt < 4; mt++) {
            int r0 = warpRow*64 + mt*16 + (lane >> 2);
            #pragma unroll
            for (int nt = 0; nt < 4; nt++) {
                int cl = warpCol*32 + nt*8 + (lane&3)*2;
                *(float2*)&tile[(r0)*132 + cl]   = make_float2(acc[mt][nt][0], acc[mt][nt][1]);
                *(float2*)&tile[(r0+8)*132 + cl] = make_float2(acc[mt][nt][2], acc[mt][nt][3]);
            }
        }
        __syncthreads();
        int r = tid >> 1, half = (tid & 1)*64;
        const float* src = tile + r*132 + half;
        float* dst = out + (size_t)(rowBase + r)*COUT + colBase + half;
        #pragma unroll
        for (int i = 0; i < 16; i++)
            *(float4*)(dst + i*4) = *(const float4*)(src + i*4);
    }
    __syncthreads();
    if (tid < 128) {
        pA[(size_t)rowBlk*COUT + colBase + tid] = ps[tid] + ps[128 + tid];
        pB[(size_t)rowBlk*COUT + colBase + tid] = pq[tid] + pq[128 + tid];
    }
}

// ---------------- final BN + relu -> output ----------------
__global__ void final_kernel(float* __restrict__ out)
{
    int i = blockIdx.x*blockDim.x + threadIdx.x;
    if (i < PT*C3) {
        int c = i & 255;
        out[i] = fmaxf(g_y[i]*g_scale[3*256 + c] + g_shift[3*256 + c], 0.f);
    }
}

// ---------------- launch ----------------
extern "C" void kernel_launch(void* const* d_in, const int* in_sizes, int n_in,
                              void* d_out, int out_size)
{
    (void)in_sizes; (void)n_in; (void)out_size;
    const float* pts = (const float*)d_in[0];
    const float* w0  = (const float*)d_in[1];
    const float* b0  = (const float*)d_in[2];
    const float* gg0 = (const float*)d_in[3];
    const float* be0 = (const float*)d_in[4];
    const float* w1  = (const float*)d_in[5];
    const float* b1  = (const float*)d_in[6];
    const float* gg1 = (const float*)d_in[7];
    const float* be1 = (const float*)d_in[8];
    const float* w2  = (const float*)d_in[9];
    const float* b2  = (const float*)d_in[10];
    const float* gg2 = (const float*)d_in[11];
    const float* be2 = (const float*)d_in[12];
    const float* wt  = (const float*)d_in[13];
    const float* bt  = (const float*)d_in[14];
    const float* ggt = (const float*)d_in[15];
    const float* bet = (const float*)d_in[16];
    float* out = (float*)d_out;

    float *dfe = nullptr, *dh1 = nullptr, *dxm = nullptr, *dy = nullptr;
    float *dpA = nullptr, *dpB = nullptr;
    __half *dw2x = nullptr, *dwtx = nullptr, *dh1x = nullptr, *dxmx = nullptr;
    cudaGetSymbolAddress((void**)&dfe, g_feats);
    cudaGetSymbolAddress((void**)&dh1, g_h1);
    cudaGetSymbolAddress((void**)&dxm, g_xm);
    cudaGetSymbolAddress((void**)&dy, g_y);
    cudaGetSymbolAddress((void**)&dpA, g_pA);
    cudaGetSymbolAddress((void**)&dpB, g_pB);
    cudaGetSymbolAddress((void**)&dw2x, g_w2x);
    cudaGetSymbolAddress((void**)&dwtx, g_wtx);
    cudaGetSymbolAddress((void**)&dh1x, g_h1x);
    cudaGetSymbolAddress((void**)&dxmx, g_xmx);

    const int SMB_TOPK = (3072 + 8*TK_PAD*32)*4 + 8*KNN*4;
    static bool attr_set = false;
    if (!attr_set) {
        cudaFuncSetAttribute(topk_kernel,        cudaFuncAttributeMaxDynamicSharedMemorySize, SMB_TOPK);
        cudaFuncSetAttribute(mma_gemm1,          cudaFuncAttributeMaxDynamicSharedMemorySize, SMBG1);
        cudaFuncSetAttribute(mma_gemm<256,2,1>,  cudaFuncAttributeMaxDynamicSharedMemorySize, SMB_GEMM);
        cudaFuncSetAttribute(mma_gemm<256,12,2>, cudaFuncAttributeMaxDynamicSharedMemorySize, SMB_GEMM);
        attr_set = true;
    }

    prep_kernel<<<(C3*C2 + C3*C3*3 + 255)/256, 256>>>(w2, wt, dw2x);
    traj_kernel<<<B_*NP/8, 256>>>(pts);
    topk_kernel<<<B_*T_*128, 256, SMB_TOPK>>>(pts);
    moment_kernel<<<512, 256>>>();
    fold0_kernel<<<1, 64>>>(w0, b0, gg0, be0);

    mma_gemm1<<<P1/128/G1_TILES, 256, SMBG1>>>(dfe, w0, b0, w1, b1, dh1, dpA, dpB);
    fold_kernel<<<C2, 256>>>(P1/128, C2, (float)P1, gg1, be1, 1);

    cvt_kernel<C2><<<dim3(P1/128, 2), 256>>>(dh1, dh1x, 1);
    mma_gemm<256,2,1><<<dim3(2, P1/128), 256, SMB_GEMM>>>(dh1x, dw2x, b2, dxm, dpA, dpB);
    fold_kernel<<<C3, 256>>>(P1/128, C3, (float)P1, gg2, be2, 2);

    cvt_kernel<C3><<<dim3(PM/128, 4), 256>>>(dxm, dxmx, 2);
    mma_gemm<256,12,2><<<dim3(2, PT/128), 256, SMB_GEMM>>>(dxmx, dwtx, bt, dy, dpA, dpB);
    fold_kernel<<<C3, 256>>>(PT/128, C3, (float)PT, ggt, bet, 3);

    final_kernel<<<(PT*C3 + 255)/256, 256>>>(out);
}